// round 8
// baseline (speedup 1.0000x reference)
#include <cuda_runtime.h>
#include <cstdint>

// ---------------------------------------------------------------------------
// Problem constants
// ---------------------------------------------------------------------------
#define BATCH 64
#define SEQ   512
#define DIM   768
#define BD    (BATCH * DIM)          // 49152
#define R192  192
#define KDIM  1536
#define PREDK 2304

#define KS_FC1  24                   // 1536 = 24 * 64
#define KS_GATE 24                   // 1536 = 24 * 64
#define KS_PRED 12                   // 2304 = 12 * 192

#define FC1_MN   (R192 * 512)        // 98304
#define GATE_MN  (R192 * 768)        // 147456
#define PRED_MN96 (96 * 512)         // 49152 (96-row padded)

// GEMM tile geometry: 96 x 128, 256-thread worker, 6x8 per thread
#define AS_PAD   104                 // padded A row (96 + 8)
#define AS_F     (32 * AS_PAD)       // 3328 floats
#define BS_F     (32 * 128)          // 4096 floats
#define STAGE_F  (AS_F + BS_F)       // 7424 floats
#define WORKER_F (2 * STAGE_F)       // 14848 floats (2 stages)
#define TOTAL_SMEM_B (2 * WORKER_F * 4)   // 118784 bytes (2 workers)

// ---------------------------------------------------------------------------
// Device scratch (zero-initialized -> padded rows deterministic)
// ---------------------------------------------------------------------------
__device__ float g_ent  [96 * PREDK];          // rows 0..63 real, 64..95 pad
__device__ float g_e    [3 * BD];              // entity state, in-place
__device__ float g_X1   [R192 * KDIM];         // fc1 input  [eA | eB]
__device__ float g_X2   [R192 * KDIM];         // gate input [u  | e ]
__device__ float g_pfc1 [KS_FC1  * FC1_MN];
__device__ float g_pgate[KS_GATE * GATE_MN];
__device__ float g_ppred[KS_PRED * PRED_MN96];

__device__ unsigned int g_bar_count = 0;
__device__ unsigned int g_bar_gen   = 0;

// ---------------------------------------------------------------------------
// Helpers
// ---------------------------------------------------------------------------
__device__ __forceinline__ unsigned long long pack2(float x, float y) {
    unsigned long long r;
    asm("mov.b64 %0, {%1, %2};" : "=l"(r) : "f"(x), "f"(y));
    return r;
}
__device__ __forceinline__ void ffma2(unsigned long long& acc,
                                      unsigned long long a,
                                      unsigned long long b) {
    asm("fma.rn.f32x2 %0, %1, %2, %3;" : "=l"(acc) : "l"(a), "l"(b), "l"(acc));
}
__device__ __forceinline__ float2 unpack2(unsigned long long v) {
    float2 f;
    asm("mov.b64 {%0, %1}, %2;" : "=f"(f.x), "=f"(f.y) : "l"(v));
    return f;
}
__device__ __forceinline__ float sigmoidf(float x) {
    return 1.0f / (1.0f + expf(-x));
}
__device__ __forceinline__ float4 ldcg4(const float* p) {
    return __ldcg(reinterpret_cast<const float4*>(p));
}
__device__ __forceinline__ void stcg4(float* p, float4 v) {
    __stcg(reinterpret_cast<float4*>(p), v);
}
__device__ __forceinline__ float4 ldg4(const float* p) {
    return __ldg(reinterpret_cast<const float4*>(p));
}
// per-half (256-thread) named barrier: ids 1 and 2
__device__ __forceinline__ void wbar(int half) {
    asm volatile("bar.sync %0, 256;" :: "r"(half + 1) : "memory");
}

__device__ __forceinline__ unsigned int atom_add_release(unsigned int* p, unsigned int v) {
    unsigned int r;
    asm volatile("atom.release.gpu.add.u32 %0, [%1], %2;"
                 : "=r"(r) : "l"(p), "r"(v) : "memory");
    return r;
}
__device__ __forceinline__ unsigned int ld_acquire(unsigned int* p) {
    unsigned int r;
    asm volatile("ld.acquire.gpu.u32 %0, [%1];" : "=r"(r) : "l"(p) : "memory");
    return r;
}
__device__ __forceinline__ void st_release(unsigned int* p, unsigned int v) {
    asm volatile("st.release.gpu.u32 [%0], %1;" :: "l"(p), "r"(v) : "memory");
}

// Grid barrier over all resident blocks (512 threads each)
__device__ __forceinline__ void grid_sync() {
    __syncthreads();
    if (threadIdx.x == 0) {
        unsigned int gen = ld_acquire(&g_bar_gen);
        unsigned int t = atom_add_release(&g_bar_count, 1u);
        if (t == gridDim.x - 1u) {
            g_bar_count = 0u;
            st_release(&g_bar_gen, gen + 1u);
        } else {
            while (ld_acquire(&g_bar_gen) == gen) { __nanosleep(32); }
        }
    }
    __syncthreads();
}

// ---------------------------------------------------------------------------
// GEMM tile: C[96 x 128] = A[96 x kchunk] * W[kchunk x 128-of-N]
// 256-thread worker; thread (tm 0..15, tn 0..15) owns rows tm*6..+5,
// cols tn*4..+3 and 64+tn*4..+3. A pairs read as LDS.64 -> direct f32x2 ops.
// 2-stage smem double buffer, register prefetch (R6-proven scheme).
// ---------------------------------------------------------------------------
__device__ void gemm_tile(int half, int ht, float* sbase,
                          const float* __restrict__ A, int lda,
                          const float* __restrict__ W, int N,
                          float* __restrict__ Pout, int kchunk)
{
    const int tm = ht >> 4;          // 0..15
    const int tn = ht & 15;          // 0..15
    const int arow = ht >> 1;        // 0..127 (A loader uses ht<192 -> 0..95)
    const int kq   = (ht & 1) * 16;  // 0 / 16
    const int brw  = ht >> 3;        // 0..31
    const int bcc  = (ht & 7) * 16;  // 0..112

    unsigned long long acc[3][8];
    #pragma unroll
    for (int i = 0; i < 3; i++)
        #pragma unroll
        for (int j = 0; j < 8; j++) acc[i][j] = 0ULL;

    const int T = kchunk >> 5;
    const bool aload = (ht < 192);
    const float* Abase = aload ? (A + (size_t)arow * lda + kq) : A;
    const float* Wbase = W + (size_t)brw * N + bcc;

    float4 Ar[4];
    float4 Br[4];

    // load tile 0 into regs
    if (aload) {
        #pragma unroll
        for (int j = 0; j < 4; j++) Ar[j] = ldcg4(Abase + j * 4);
    }
    #pragma unroll
    for (int j = 0; j < 4; j++) Br[j] = ldg4(Wbase + j * 4);

    wbar(half);                        // previous smem users done
    {
        float* As = sbase;
        float* Bs = sbase + AS_F;
        if (aload) {
            const float* av = reinterpret_cast<const float*>(Ar);
            #pragma unroll
            for (int j = 0; j < 16; j++)
                As[(kq + j) * AS_PAD + arow] = av[j];
        }
        #pragma unroll
        for (int j = 0; j < 4; j++)
            *(float4*)&Bs[brw * 128 + bcc + j * 4] = Br[j];
    }
    // prefetch tile 1
    if (T > 1) {
        if (aload) {
            #pragma unroll
            for (int j = 0; j < 4; j++) Ar[j] = ldcg4(Abase + 32 + j * 4);
        }
        const float* wp = Wbase + 32 * N;
        #pragma unroll
        for (int j = 0; j < 4; j++) Br[j] = ldg4(wp + j * 4);
    }
    wbar(half);                        // stage 0 visible

    int p = 0;
    for (int t = 0; t < T; t++) {
        const float* As = sbase + p * STAGE_F;
        const float* Bs = As + AS_F;
        #pragma unroll
        for (int kk = 0; kk < 32; kk++) {
            const float* arowp = &As[kk * AS_PAD + tm * 6];
            unsigned long long ap0 = *(const unsigned long long*)(arowp);
            unsigned long long ap1 = *(const unsigned long long*)(arowp + 2);
            unsigned long long ap2 = *(const unsigned long long*)(arowp + 4);
            float4 b0 = *(const float4*)&Bs[kk * 128 + tn * 4];
            float4 b1 = *(const float4*)&Bs[kk * 128 + 64 + tn * 4];
            unsigned long long bd;
            bd = pack2(b0.x, b0.x); ffma2(acc[0][0], ap0, bd); ffma2(acc[1][0], ap1, bd); ffma2(acc[2][0], ap2, bd);
            bd = pack2(b0.y, b0.y); ffma2(acc[0][1], ap0, bd); ffma2(acc[1][1], ap1, bd); ffma2(acc[2][1], ap2, bd);
            bd = pack2(b0.z, b0.z); ffma2(acc[0][2], ap0, bd); ffma2(acc[1][2], ap1, bd); ffma2(acc[2][2], ap2, bd);
            bd = pack2(b0.w, b0.w); ffma2(acc[0][3], ap0, bd); ffma2(acc[1][3], ap1, bd); ffma2(acc[2][3], ap2, bd);
            bd = pack2(b1.x, b1.x); ffma2(acc[0][4], ap0, bd); ffma2(acc[1][4], ap1, bd); ffma2(acc[2][4], ap2, bd);
            bd = pack2(b1.y, b1.y); ffma2(acc[0][5], ap0, bd); ffma2(acc[1][5], ap1, bd); ffma2(acc[2][5], ap2, bd);
            bd = pack2(b1.z, b1.z); ffma2(acc[0][6], ap0, bd); ffma2(acc[1][6], ap1, bd); ffma2(acc[2][6], ap2, bd);
            bd = pack2(b1.w, b1.w); ffma2(acc[0][7], ap0, bd); ffma2(acc[1][7], ap1, bd); ffma2(acc[2][7], ap2, bd);
        }

        if (t + 1 < T) {
            // store prefetched tile t+1 into the other stage
            float* Aw = sbase + (1 - p) * STAGE_F;
            float* Bw = Aw + AS_F;
            if (aload) {
                const float* av = reinterpret_cast<const float*>(Ar);
                #pragma unroll
                for (int j = 0; j < 16; j++)
                    Aw[(kq + j) * AS_PAD + arow] = av[j];
            }
            #pragma unroll
            for (int j = 0; j < 4; j++)
                *(float4*)&Bw[brw * 128 + bcc + j * 4] = Br[j];
            // prefetch tile t+2
            if (t + 2 < T) {
                int kb = (t + 2) << 5;
                if (aload) {
                    #pragma unroll
                    for (int j = 0; j < 4; j++) Ar[j] = ldcg4(Abase + kb + j * 4);
                }
                const float* wp = Wbase + (size_t)kb * N;
                #pragma unroll
                for (int j = 0; j < 4; j++) Br[j] = ldg4(wp + j * 4);
            }
            wbar(half);
            p ^= 1;
        }
    }

    // epilogue: 3 row-pairs x 2 col-groups
    #pragma unroll
    for (int i = 0; i < 3; i++) {
        float2 u0 = unpack2(acc[i][0]);
        float2 u1 = unpack2(acc[i][1]);
        float2 u2 = unpack2(acc[i][2]);
        float2 u3 = unpack2(acc[i][3]);
        float2 v0 = unpack2(acc[i][4]);
        float2 v1 = unpack2(acc[i][5]);
        float2 v2 = unpack2(acc[i][6]);
        float2 v3 = unpack2(acc[i][7]);
        float* row0 = Pout + (size_t)(tm * 6 + 2 * i) * N;
        float* row1 = row0 + N;
        stcg4(row0 + tn * 4,      make_float4(u0.x, u1.x, u2.x, u3.x));
        stcg4(row0 + 64 + tn * 4, make_float4(v0.x, v1.x, v2.x, v3.x));
        stcg4(row1 + tn * 4,      make_float4(u0.y, u1.y, u2.y, u3.y));
        stcg4(row1 + 64 + tn * 4, make_float4(v0.y, v1.y, v2.y, v3.y));
    }
}

// X1 slot tables. Pairs: p0=[e1|e2], p1=[e0|e2], p2=[e0|e1]
__device__ __constant__ int D1ROW[3] = {1, 0, 0};
__device__ __constant__ int D1OFF[3] = {0, 0, 768};
__device__ __constant__ int D2ROW[3] = {2, 2, 1};
__device__ __constant__ int D2OFF[3] = {0, 768, 768};

// ---------------------------------------------------------------------------
// Phase jobs (per 256-thread half)
// ---------------------------------------------------------------------------
__device__ void maxpool_job(int half, int t, float* sb, int bk,
                            const float* __restrict__ enc,
                            const int* __restrict__ ep,
                            const float* __restrict__ projW,
                            const float* __restrict__ projb,
                            float* __restrict__ out_score)
{
    float* red = sb;
    int b = bk / 3, k = bk - b * 3;
    int s0 = ep[bk * 2 + 0];
    int s1 = ep[bk * 2 + 1];

    float m0 = -1e30f, m1 = -1e30f, m2 = -1e30f;
    const float* base = enc + (size_t)b * SEQ * DIM;
    #pragma unroll 4
    for (int s = s0; s <= s1; s++) {
        const float* row = base + s * DIM;
        m0 = fmaxf(m0, __ldg(row + t));
        m1 = fmaxf(m1, __ldg(row + t + 256));
        m2 = fmaxf(m2, __ldg(row + t + 512));
    }

    size_t x1a = (size_t)(D1ROW[k] * 64 + b) * KDIM + D1OFF[k];
    size_t x1b = (size_t)(D2ROW[k] * 64 + b) * KDIM + D2OFF[k];
    size_t x2r = (size_t)(k * 64 + b) * KDIM + 768;
    size_t er  = (size_t)(k * 64 + b) * DIM;
    size_t eno = (size_t)b * PREDK + k * DIM;

    #pragma unroll
    for (int q = 0; q < 3; q++) {
        int d = t + q * 256;
        float m = (q == 0) ? m0 : (q == 1) ? m1 : m2;
        __stcg(g_ent + eno + d, m);
        __stcg(g_e   + er  + d, m);
        __stcg(g_X1  + x1a + d, m);
        __stcg(g_X1  + x1b + d, m);
        __stcg(g_X2  + x2r + d, m);
    }

    wbar(half);                         // smem may be in use by prior job
    red[t] = m0 * projW[t] + m1 * projW[t + 256] + m2 * projW[t + 512];
    wbar(half);
    for (int off = 128; off > 0; off >>= 1) {
        if (t < off) red[t] += red[t + off];
        wbar(half);
    }
    if (t == 0) out_score[bk] = sigmoidf(red[0] + projb[0]);
    wbar(half);
}

__device__ void finish1_job(int half, int t, float* sb, int r,
                            const float* __restrict__ b1,
                            const float* __restrict__ W2, const float* __restrict__ b2,
                            const float* __restrict__ ArW, const float* __restrict__ Arb)
{
    float* sh_h = sb;                  // 512
    float* red  = sb + 512;            // 5*256
    float* sh_s = sb + 512 + 1280;     // 8

    wbar(half);
    for (int j = t; j < 512; j += 256) {
        float s = b1[j];
        #pragma unroll
        for (int z = 0; z < KS_FC1; z++)
            s += __ldcg(g_pfc1 + (size_t)z * FC1_MN + r * 512 + j);
        sh_h[j] = fmaxf(s, 0.0f);
    }
    wbar(half);

    float ps[5] = {0, 0, 0, 0, 0};
    for (int j = t; j < 512; j += 256) {
        float h = sh_h[j];
        #pragma unroll
        for (int c = 0; c < 5; c++) ps[c] += h * W2[j * 5 + c];
    }
    #pragma unroll
    for (int c = 0; c < 5; c++) red[c * 256 + t] = ps[c];
    wbar(half);
    for (int off = 128; off > 0; off >>= 1) {
        if (t < off) {
            #pragma unroll
            for (int c = 0; c < 5; c++) red[c * 256 + t] += red[c * 256 + t + off];
        }
        wbar(half);
    }
    if (t < 5) sh_s[t] = sigmoidf(red[t * 256] + b2[t]);
    wbar(half);

    float s0 = sh_s[0], s1 = sh_s[1], s2 = sh_s[2], s3 = sh_s[3], s4 = sh_s[4];
    const float* epv = g_e + (size_t)r * DIM;
    float* up = g_X2 + (size_t)r * KDIM;          // u -> left half of X2
    for (int d = t; d < DIM; d += 256) {
        float a = Arb[d] + s0 * ArW[d] + s1 * ArW[DIM + d] + s2 * ArW[2 * DIM + d]
                + s3 * ArW[3 * DIM + d] + s4 * ArW[4 * DIM + d];
        __stcg(up + d, a * __ldcg(epv + d));
    }
}

__device__ void pred_finish_job(int half, int t, float* sb, int b,
                                const float* __restrict__ b1,
                                const float* __restrict__ W2,
                                const float* __restrict__ b2,
                                float* __restrict__ rel_out)
{
    float* sh_h = sb;
    float* red  = sb + 512;

    wbar(half);
    for (int j = t; j < 512; j += 256) {
        float s = b1[j];
        #pragma unroll
        for (int z = 0; z < KS_PRED; z++)
            s += __ldcg(g_ppred + (size_t)z * PRED_MN96 + b * 512 + j);
        sh_h[j] = fmaxf(s, 0.0f);
    }
    wbar(half);

    float ps[5] = {0, 0, 0, 0, 0};
    for (int j = t; j < 512; j += 256) {
        float h = sh_h[j];
        #pragma unroll
        for (int c = 0; c < 5; c++) ps[c] += h * W2[j * 5 + c];
    }
    #pragma unroll
    for (int c = 0; c < 5; c++) red[c * 256 + t] = ps[c];
    wbar(half);
    for (int off = 128; off > 0; off >>= 1) {
        if (t < off) {
            #pragma unroll
            for (int c = 0; c < 5; c++) red[c * 256 + t] += red[c * 256 + t + off];
        }
        wbar(half);
    }
    if (t < 5) rel_out[b * 5 + t] = red[t * 256] + b2[t];
}

// ---------------------------------------------------------------------------
// Persistent fused kernel: 512 threads = two 256-thread workers
// ---------------------------------------------------------------------------
__global__ void __launch_bounds__(512, 1)
fused_kernel(const float* __restrict__ enc, const int* __restrict__ ep,
             const float* __restrict__ ArW, const float* __restrict__ Arb,
             const float* __restrict__ VrW1, const float* __restrict__ Vrb1,
             const float* __restrict__ VrW2, const float* __restrict__ Vrb2,
             const float* __restrict__ gateW, const float* __restrict__ gateb,
             const float* __restrict__ predW1, const float* __restrict__ predb1,
             const float* __restrict__ predW2, const float* __restrict__ predb2,
             const float* __restrict__ projW, const float* __restrict__ projb,
             float* __restrict__ out_rel, float* __restrict__ out_score,
             float* __restrict__ out_final)
{
    extern __shared__ __align__(16) float smem_u[];

    const int half = threadIdx.x >> 8;
    const int ht   = threadIdx.x & 255;
    float* sbase = smem_u + half * WORKER_F;

    const int nb = gridDim.x;
    const int wid     = blockIdx.x * 2 + half;
    const int wstride = 2 * nb;              // 296 workers

    // ---- Phase 0: span max-pool (+ scores, X1/X2 init) ----
    for (int job = wid; job < R192; job += wstride)
        maxpool_job(half, ht, sbase, job, enc, ep, projW, projb, out_score);
    grid_sync();

    for (int it = 0; it < 5; it++) {
        // ---- P1: fc1 GEMM partials (192) + pred GEMM (48, iter 0) ----
        int nj = (it == 0) ? (192 + 48) : 192;
        for (int job = wid; job < nj; job += wstride) {
            if (job < 192) {
                int z = job >> 3, rem = job & 7;        // z 0..23
                int m0 = (rem >> 2) * 96, n0 = (rem & 3) * 128;
                int k0 = z * 64;
                gemm_tile(half, ht, sbase,
                          g_X1 + (size_t)m0 * KDIM + k0, KDIM,
                          VrW1 + (size_t)k0 * 512 + n0, 512,
                          g_pfc1 + (size_t)z * FC1_MN + m0 * 512 + n0, 64);
            } else {
                int j = job - 192;                       // 0..47
                int z = j >> 2, n0 = (j & 3) * 128;      // z 0..11
                int k0 = z * 192;
                gemm_tile(half, ht, sbase,
                          g_ent + k0, PREDK,
                          predW1 + (size_t)k0 * 512 + n0, 512,
                          g_ppred + (size_t)z * PRED_MN96 + n0, 192);
            }
        }
        grid_sync();

        // ---- P2: fc1 finish -> u (+ pred finish on iter 0) ----
        nj = (it == 0) ? 256 : 192;
        for (int job = wid; job < nj; job += wstride) {
            if (job < 192) finish1_job(half, ht, sbase, job, Vrb1, VrW2, Vrb2, ArW, Arb);
            else           pred_finish_job(half, ht, sbase, job - 192,
                                           predb1, predW2, predb2, out_rel);
        }
        grid_sync();

        // ---- P3: gate GEMM partials (288) ----
        for (int job = wid; job < 288; job += wstride) {
            int z = job / 12, rem = job % 12;            // z 0..23
            int m0 = (rem / 6) * 96, n0 = (rem % 6) * 128;
            int k0 = z * 64;
            gemm_tile(half, ht, sbase,
                      g_X2 + (size_t)m0 * KDIM + k0, KDIM,
                      gateW + (size_t)k0 * 768 + n0, 768,
                      g_pgate + (size_t)z * GATE_MN + m0 * 768 + n0, 64);
        }
        grid_sync();

        // ---- P4: gate blend; in-place e update + X1/X2 scatter ----
        bool last = (it == 4);
        int tg = blockIdx.x * 512 + threadIdx.x;
        for (int q = tg; q < GATE_MN / 4; q += nb * 512) {
            int idx = q * 4;
            int r = idx / 768, n = idx - r * 768;
            int p = r >> 6, b = r & 63;
            float4 s = *(const float4*)(gateb + n);
            #pragma unroll
            for (int z = 0; z < KS_GATE; z++) {
                float4 pv = ldcg4(g_pgate + (size_t)z * GATE_MN + idx);
                s.x += pv.x; s.y += pv.y; s.z += pv.z; s.w += pv.w;
            }
            float4 uv = ldcg4(g_X2 + (size_t)r * KDIM + n);   // u (left half)
            float4 ev = ldcg4(g_e + idx);
            float4 res; float gg;
            gg = sigmoidf(s.x); res.x = gg * ev.x + (1.0f - gg) * uv.x;
            gg = sigmoidf(s.y); res.y = gg * ev.y + (1.0f - gg) * uv.y;
            gg = sigmoidf(s.z); res.z = gg * ev.z + (1.0f - gg) * uv.z;
            gg = sigmoidf(s.w); res.w = gg * ev.w + (1.0f - gg) * uv.w;
            if (last) {
                *(float4*)(out_final + (size_t)b * PREDK + p * DIM + n) = res;
            } else {
                stcg4(g_e + idx, res);
                stcg4(g_X2 + (size_t)r * KDIM + 768 + n, res);
                stcg4(g_X1 + (size_t)(D1ROW[p] * 64 + b) * KDIM + D1OFF[p] + n, res);
                stcg4(g_X1 + (size_t)(D2ROW[p] * 64 + b) * KDIM + D2OFF[p] + n, res);
            }
        }
        if (!last) grid_sync();
    }
}

// ---------------------------------------------------------------------------
// Launcher
// ---------------------------------------------------------------------------
extern "C" void kernel_launch(void* const* d_in, const int* in_sizes, int n_in,
                              void* d_out, int out_size)
{
    const float* encoding = (const float*)d_in[0];
    const int*   ent_pos  = (const int*)  d_in[1];
    const float* Ar_W     = (const float*)d_in[2];
    const float* Ar_b     = (const float*)d_in[3];
    const float* Vr_W1    = (const float*)d_in[4];
    const float* Vr_b1    = (const float*)d_in[5];
    const float* Vr_W2    = (const float*)d_in[6];
    const float* Vr_b2    = (const float*)d_in[7];
    const float* gate_W   = (const float*)d_in[8];
    const float* gate_b   = (const float*)d_in[9];
    const float* pred_W1  = (const float*)d_in[10];
    const float* pred_b1  = (const float*)d_in[11];
    const float* pred_W2  = (const float*)d_in[12];
    const float* pred_b2  = (const float*)d_in[13];
    const float* proj_W   = (const float*)d_in[14];
    const float* proj_b   = (const float*)d_in[15];

    float* out = (float*)d_out;
    float* out_rel   = out;              // (64,5)
    float* out_score = out + 320;        // (64,3)
    float* out_final = out + 512;        // (64,3,768)

    int dev = 0;
    cudaGetDevice(&dev);
    int sms = 148;
    cudaDeviceGetAttribute(&sms, cudaDevAttrMultiProcessorCount, dev);

    cudaFuncSetAttribute(fused_kernel,
                         cudaFuncAttributeMaxDynamicSharedMemorySize,
                         TOTAL_SMEM_B);

    fused_kernel<<<sms, 512, TOTAL_SMEM_B>>>(
        encoding, ent_pos, Ar_W, Ar_b,
        Vr_W1, Vr_b1, Vr_W2, Vr_b2,
        gate_W, gate_b,
        pred_W1, pred_b1, pred_W2, pred_b2,
        proj_W, proj_b,
        out_rel, out_score, out_final);

    (void)in_sizes; (void)n_in; (void)out_size;
}

// round 9
// speedup vs baseline: 1.3356x; 1.3356x over previous
#include <cuda_runtime.h>
#include <cstdint>

// ---------------------------------------------------------------------------
// Problem constants
// ---------------------------------------------------------------------------
#define BATCH 64
#define SEQ   512
#define DIM   768
#define BD    (BATCH * DIM)          // 49152
#define R192  192
#define KDIM  1536
#define PREDK 2304

#define KS_FC1  12                   // 1536 = 12 * 128
#define KS_GATE 8                    // 1536 = 8 * 192
#define KS_PRED 12                   // 2304 = 12 * 192

#define FC1_MN  (R192 * 512)         // 98304
#define GATE_MN (R192 * 768)         // 147456
#define PRED_MN (BATCH * 512)        // 32768

// smem: per worker 2 stages x (As[32][72] + Bs[32][72]) in floats
#define AS_PITCH 72
#define AS_F     (32 * AS_PITCH)     // 2304
#define BS_F     (32 * AS_PITCH)     // 2304
#define STAGE_F  (AS_F + BS_F)       // 4608
#define WORKER_F (2 * STAGE_F)       // 9216
#define TOTAL_SMEM_B (2 * WORKER_F * 4)   // 73728 bytes

// ---------------------------------------------------------------------------
// Device scratch
// ---------------------------------------------------------------------------
__device__ float g_ent  [BATCH * PREDK];
__device__ float g_e    [3 * BD];              // entity state, in-place
__device__ float g_X1   [R192 * KDIM];         // fc1 input  [eA | eB]
__device__ float g_X2   [R192 * KDIM];         // gate input [u  | e ]
__device__ float g_pfc1 [KS_FC1  * FC1_MN];
__device__ float g_pgate[KS_GATE * GATE_MN];
__device__ float g_ppred[KS_PRED * PRED_MN];

__device__ unsigned int g_bar_count = 0;
__device__ unsigned int g_bar_gen   = 0;

// ---------------------------------------------------------------------------
// Helpers
// ---------------------------------------------------------------------------
__device__ __forceinline__ float sigmoidf(float x) {
    return 1.0f / (1.0f + expf(-x));
}
__device__ __forceinline__ float4 ldcg4(const float* p) {
    return __ldcg(reinterpret_cast<const float4*>(p));
}
__device__ __forceinline__ void stcg4(float* p, float4 v) {
    __stcg(reinterpret_cast<float4*>(p), v);
}
__device__ __forceinline__ void stcg2(float* p, float2 v) {
    __stcg(reinterpret_cast<float2*>(p), v);
}
__device__ __forceinline__ float4 ldg4(const float* p) {
    return __ldg(reinterpret_cast<const float4*>(p));
}
__device__ __forceinline__ float f2tf32f(float x) {
    uint32_t r;
    asm("cvt.rna.tf32.f32 %0, %1;" : "=r"(r) : "f"(x));
    return __uint_as_float(r);
}
__device__ __forceinline__ void mma_tf32(float* d,
    uint32_t a0, uint32_t a1, uint32_t a2, uint32_t a3,
    uint32_t b0, uint32_t b1)
{
    asm volatile(
        "mma.sync.aligned.m16n8k8.row.col.f32.tf32.tf32.f32 "
        "{%0,%1,%2,%3}, {%4,%5,%6,%7}, {%8,%9}, {%0,%1,%2,%3};"
        : "+f"(d[0]), "+f"(d[1]), "+f"(d[2]), "+f"(d[3])
        : "r"(a0), "r"(a1), "r"(a2), "r"(a3), "r"(b0), "r"(b1));
}
// per-half (256-thread) named barrier: ids 1 and 2
__device__ __forceinline__ void wbar(int half) {
    asm volatile("bar.sync %0, 256;" :: "r"(half + 1) : "memory");
}

__device__ __forceinline__ unsigned int atom_add_release(unsigned int* p, unsigned int v) {
    unsigned int r;
    asm volatile("atom.release.gpu.add.u32 %0, [%1], %2;"
                 : "=r"(r) : "l"(p), "r"(v) : "memory");
    return r;
}
__device__ __forceinline__ unsigned int ld_acquire(unsigned int* p) {
    unsigned int r;
    asm volatile("ld.acquire.gpu.u32 %0, [%1];" : "=r"(r) : "l"(p) : "memory");
    return r;
}
__device__ __forceinline__ void st_release(unsigned int* p, unsigned int v) {
    asm volatile("st.release.gpu.u32 [%0], %1;" :: "l"(p), "r"(v) : "memory");
}

// Grid barrier over all resident blocks (512 threads each)
__device__ __forceinline__ void grid_sync() {
    __syncthreads();
    if (threadIdx.x == 0) {
        unsigned int gen = ld_acquire(&g_bar_gen);
        unsigned int t = atom_add_release(&g_bar_count, 1u);
        if (t == gridDim.x - 1u) {
            g_bar_count = 0u;
            st_release(&g_bar_gen, gen + 1u);
        } else {
            while (ld_acquire(&g_bar_gen) == gen) { __nanosleep(32); }
        }
    }
    __syncthreads();
}

// ---------------------------------------------------------------------------
// Stage store: A (k-major, tf32-converted, scalar scatter) + B (k-major, f4)
// ---------------------------------------------------------------------------
__device__ __forceinline__ void stage_store(float* stage, int am, int akq,
                                            int bkk, int bnq,
                                            float4 Ar0, float4 Ar1,
                                            float4 Br0, float4 Br1)
{
    float* As = stage;
    float* Bs = stage + AS_F;
    As[(akq + 0) * AS_PITCH + am] = f2tf32f(Ar0.x);
    As[(akq + 1) * AS_PITCH + am] = f2tf32f(Ar0.y);
    As[(akq + 2) * AS_PITCH + am] = f2tf32f(Ar0.z);
    As[(akq + 3) * AS_PITCH + am] = f2tf32f(Ar0.w);
    As[(akq + 4) * AS_PITCH + am] = f2tf32f(Ar1.x);
    As[(akq + 5) * AS_PITCH + am] = f2tf32f(Ar1.y);
    As[(akq + 6) * AS_PITCH + am] = f2tf32f(Ar1.z);
    As[(akq + 7) * AS_PITCH + am] = f2tf32f(Ar1.w);
    float4 v0 = make_float4(f2tf32f(Br0.x), f2tf32f(Br0.y),
                            f2tf32f(Br0.z), f2tf32f(Br0.w));
    float4 v1 = make_float4(f2tf32f(Br1.x), f2tf32f(Br1.y),
                            f2tf32f(Br1.z), f2tf32f(Br1.w));
    *(float4*)&Bs[bkk * AS_PITCH + bnq]     = v0;
    *(float4*)&Bs[bkk * AS_PITCH + bnq + 4] = v1;
}

// ---------------------------------------------------------------------------
// GEMM tile via tensor cores (tf32 mma.sync):
//   C[64 x 64] = A[64 x kchunk] * W[kchunk x 64-of-N]
// 256-thread worker = 8 warps; warp (wm = w&3, wn = w>>2) computes the
// m16 slab wm, n32 half wn as 4 x m16n8k8 fragments.
// 2-stage smem double buffer, register prefetch, 1 wbar per ktile.
// ---------------------------------------------------------------------------
__device__ void gemm_tile(int half, int ht, float* sbase,
                          const float* __restrict__ A, int lda,
                          const float* __restrict__ W, int N,
                          float* __restrict__ Pout, int kchunk)
{
    const int lane = ht & 31;
    const int wrp  = ht >> 5;         // 0..7
    const int wm = wrp & 3;           // m16 slab
    const int wn = wrp >> 2;          // n32 half
    const int g = lane >> 2;          // 0..7
    const int t = lane & 3;           // 0..3

    // loader mapping (conflict-free STS for A; coalesced globals)
    const int am  = ht & 63;          // A row 0..63
    const int akq = (ht >> 6) * 8;    // k sub-offset 0,8,16,24
    const int bkk = ht >> 3;          // B k row 0..31
    const int bnq = (ht & 7) * 8;     // B col 0..56

    float acc[4][4];
    #pragma unroll
    for (int f = 0; f < 4; f++)
        #pragma unroll
        for (int i = 0; i < 4; i++) acc[f][i] = 0.0f;

    const int T = kchunk >> 5;
    const float* Abase = A + (size_t)am * lda + akq;
    const float* Wbase = W + (size_t)bkk * N + bnq;

    // load ktile 0 into regs
    float4 Ar0 = ldcg4(Abase);
    float4 Ar1 = ldcg4(Abase + 4);
    float4 Br0 = ldg4(Wbase);
    float4 Br1 = ldg4(Wbase + 4);

    wbar(half);                        // previous smem users done
    stage_store(sbase, am, akq, bkk, bnq, Ar0, Ar1, Br0, Br1);
    if (T > 1) {                       // prefetch ktile 1
        Ar0 = ldcg4(Abase + 32);
        Ar1 = ldcg4(Abase + 36);
        const float* wp = Wbase + 32 * N;
        Br0 = ldg4(wp);
        Br1 = ldg4(wp + 4);
    }
    wbar(half);                        // stage 0 visible

    int p = 0;
    for (int tt = 0; tt < T; tt++) {
        const float* As = sbase + p * STAGE_F;
        const float* Bs = As + AS_F;
        const float* Ab = As + wm * 16;
        const float* Bb = Bs + wn * 32;
        #pragma unroll
        for (int q = 0; q < 4; q++) {
            const int kr = q * 8 + t;
            uint32_t a0 = __float_as_uint(Ab[kr * AS_PITCH + g]);
            uint32_t a1 = __float_as_uint(Ab[kr * AS_PITCH + g + 8]);
            uint32_t a2 = __float_as_uint(Ab[(kr + 4) * AS_PITCH + g]);
            uint32_t a3 = __float_as_uint(Ab[(kr + 4) * AS_PITCH + g + 8]);
            #pragma unroll
            for (int f = 0; f < 4; f++) {
                uint32_t b0 = __float_as_uint(Bb[kr * AS_PITCH + f * 8 + g]);
                uint32_t b1 = __float_as_uint(Bb[(kr + 4) * AS_PITCH + f * 8 + g]);
                mma_tf32(acc[f], a0, a1, a2, a3, b0, b1);
            }
        }

        if (tt + 1 < T) {
            stage_store(sbase + (1 - p) * STAGE_F, am, akq, bkk, bnq,
                        Ar0, Ar1, Br0, Br1);
            if (tt + 2 < T) {
                int kb = (tt + 2) << 5;
                Ar0 = ldcg4(Abase + kb);
                Ar1 = ldcg4(Abase + kb + 4);
                const float* wp = Wbase + (size_t)kb * N;
                Br0 = ldg4(wp);
                Br1 = ldg4(wp + 4);
            }
            wbar(half);
            p ^= 1;
        }
    }

    // epilogue: frag (row g / g+8, cols 2t, 2t+1)
    const int row0 = wm * 16 + g;
    float* r0p = Pout + (size_t)row0 * N;
    float* r1p = r0p + 8 * N;
    #pragma unroll
    for (int f = 0; f < 4; f++) {
        int col = wn * 32 + f * 8 + 2 * t;
        stcg2(r0p + col, make_float2(acc[f][0], acc[f][1]));
        stcg2(r1p + col, make_float2(acc[f][2], acc[f][3]));
    }
}

// X1 slot tables. Pairs: p0=[e1|e2], p1=[e0|e2], p2=[e0|e1]
__device__ __constant__ int D1ROW[3] = {1, 0, 0};
__device__ __constant__ int D1OFF[3] = {0, 0, 768};
__device__ __constant__ int D2ROW[3] = {2, 2, 1};
__device__ __constant__ int D2OFF[3] = {0, 768, 768};

// ---------------------------------------------------------------------------
// Phase jobs (per 256-thread half)
// ---------------------------------------------------------------------------
__device__ void maxpool_job(int half, int t, float* sb, int bk,
                            const float* __restrict__ enc,
                            const int* __restrict__ ep,
                            const float* __restrict__ projW,
                            const float* __restrict__ projb,
                            float* __restrict__ out_score)
{
    float* red = sb;
    int b = bk / 3, k = bk - b * 3;
    int s0 = ep[bk * 2 + 0];
    int s1 = ep[bk * 2 + 1];

    float m0 = -1e30f, m1 = -1e30f, m2 = -1e30f;
    const float* base = enc + (size_t)b * SEQ * DIM;
    #pragma unroll 4
    for (int s = s0; s <= s1; s++) {
        const float* row = base + s * DIM;
        m0 = fmaxf(m0, __ldg(row + t));
        m1 = fmaxf(m1, __ldg(row + t + 256));
        m2 = fmaxf(m2, __ldg(row + t + 512));
    }

    size_t x1a = (size_t)(D1ROW[k] * 64 + b) * KDIM + D1OFF[k];
    size_t x1b = (size_t)(D2ROW[k] * 64 + b) * KDIM + D2OFF[k];
    size_t x2r = (size_t)(k * 64 + b) * KDIM + 768;
    size_t er  = (size_t)(k * 64 + b) * DIM;
    size_t eno = (size_t)b * PREDK + k * DIM;

    #pragma unroll
    for (int q = 0; q < 3; q++) {
        int d = t + q * 256;
        float m = (q == 0) ? m0 : (q == 1) ? m1 : m2;
        __stcg(g_ent + eno + d, m);
        __stcg(g_e   + er  + d, m);
        __stcg(g_X1  + x1a + d, m);
        __stcg(g_X1  + x1b + d, m);
        __stcg(g_X2  + x2r + d, m);
    }

    wbar(half);                         // smem may be in use by prior job
    red[t] = m0 * projW[t] + m1 * projW[t + 256] + m2 * projW[t + 512];
    wbar(half);
    for (int off = 128; off > 0; off >>= 1) {
        if (t < off) red[t] += red[t + off];
        wbar(half);
    }
    if (t == 0) out_score[bk] = sigmoidf(red[0] + projb[0]);
    wbar(half);
}

__device__ void finish1_job(int half, int t, float* sb, int r,
                            const float* __restrict__ b1,
                            const float* __restrict__ W2, const float* __restrict__ b2,
                            const float* __restrict__ ArW, const float* __restrict__ Arb)
{
    float* sh_h = sb;                  // 512
    float* red  = sb + 512;            // 5*256
    float* sh_s = sb + 512 + 1280;     // 8

    wbar(half);                        // protect smem from previous job
    for (int j = t; j < 512; j += 256) {
        float s = b1[j];
        #pragma unroll
        for (int z = 0; z < KS_FC1; z++)
            s += __ldcg(g_pfc1 + (size_t)z * FC1_MN + r * 512 + j);
        sh_h[j] = fmaxf(s, 0.0f);
    }
    wbar(half);

    float ps[5] = {0, 0, 0, 0, 0};
    for (int j = t; j < 512; j += 256) {
        float h = sh_h[j];
        #pragma unroll
        for (int c = 0; c < 5; c++) ps[c] += h * W2[j * 5 + c];
    }
    #pragma unroll
    for (int c = 0; c < 5; c++) red[c * 256 + t] = ps[c];
    wbar(half);
    for (int off = 128; off > 0; off >>= 1) {
        if (t < off) {
            #pragma unroll
            for (int c = 0; c < 5; c++) red[c * 256 + t] += red[c * 256 + t + off];
        }
        wbar(half);
    }
    if (t < 5) sh_s[t] = sigmoidf(red[t * 256] + b2[t]);
    wbar(half);

    float s0 = sh_s[0], s1 = sh_s[1], s2 = sh_s[2], s3 = sh_s[3], s4 = sh_s[4];
    const float* epv = g_e + (size_t)r * DIM;
    float* up = g_X2 + (size_t)r * KDIM;          // u -> left half of X2
    for (int d = t; d < DIM; d += 256) {
        float a = Arb[d] + s0 * ArW[d] + s1 * ArW[DIM + d] + s2 * ArW[2 * DIM + d]
                + s3 * ArW[3 * DIM + d] + s4 * ArW[4 * DIM + d];
        __stcg(up + d, a * __ldcg(epv + d));
    }
}

__device__ void pred_finish_job(int half, int t, float* sb, int b,
                                const float* __restrict__ b1,
                                const float* __restrict__ W2,
                                const float* __restrict__ b2,
                                float* __restrict__ rel_out)
{
    float* sh_h = sb;
    float* red  = sb + 512;

    wbar(half);
    for (int j = t; j < 512; j += 256) {
        float s = b1[j];
        #pragma unroll
        for (int z = 0; z < KS_PRED; z++)
            s += __ldcg(g_ppred + (size_t)z * PRED_MN + b * 512 + j);
        sh_h[j] = fmaxf(s, 0.0f);
    }
    wbar(half);

    float ps[5] = {0, 0, 0, 0, 0};
    for (int j = t; j < 512; j += 256) {
        float h = sh_h[j];
        #pragma unroll
        for (int c = 0; c < 5; c++) ps[c] += h * W2[j * 5 + c];
    }
    #pragma unroll
    for (int c = 0; c < 5; c++) red[c * 256 + t] = ps[c];
    wbar(half);
    for (int off = 128; off > 0; off >>= 1) {
        if (t < off) {
            #pragma unroll
            for (int c = 0; c < 5; c++) red[c * 256 + t] += red[c * 256 + t + off];
        }
        wbar(half);
    }
    if (t < 5) rel_out[b * 5 + t] = red[t * 256] + b2[t];
}

// ---------------------------------------------------------------------------
// Persistent fused kernel: 512 threads = two 256-thread workers
// ---------------------------------------------------------------------------
__global__ void __launch_bounds__(512, 1)
fused_kernel(const float* __restrict__ enc, const int* __restrict__ ep,
             const float* __restrict__ ArW, const float* __restrict__ Arb,
             const float* __restrict__ VrW1, const float* __restrict__ Vrb1,
             const float* __restrict__ VrW2, const float* __restrict__ Vrb2,
             const float* __restrict__ gateW, const float* __restrict__ gateb,
             const float* __restrict__ predW1, const float* __restrict__ predb1,
             const float* __restrict__ predW2, const float* __restrict__ predb2,
             const float* __restrict__ projW, const float* __restrict__ projb,
             float* __restrict__ out_rel, float* __restrict__ out_score,
             float* __restrict__ out_final)
{
    extern __shared__ __align__(16) float smem_u[];

    const int half = threadIdx.x >> 8;
    const int ht   = threadIdx.x & 255;
    float* sbase = smem_u + half * WORKER_F;

    const int nb = gridDim.x;
    const int wid     = blockIdx.x * 2 + half;
    const int wstride = 2 * nb;              // 296 workers

    // ---- Phase 0: span max-pool (+ scores, X1/X2 init) ----
    for (int job = wid; job < R192; job += wstride)
        maxpool_job(half, ht, sbase, job, enc, ep, projW, projb, out_score);
    grid_sync();

    for (int it = 0; it < 5; it++) {
        // ---- P1: fc1 GEMM partials (288) + pred GEMM (96, iter 0) ----
        int nj = (it == 0) ? (288 + 96) : 288;
        for (int job = wid; job < nj; job += wstride) {
            if (job < 288) {
                int z = job / 24, rem = job % 24;
                int m0 = (rem >> 3) * 64, n0 = (rem & 7) * 64;
                int k0 = z * 128;
                gemm_tile(half, ht, sbase,
                          g_X1 + (size_t)m0 * KDIM + k0, KDIM,
                          VrW1 + (size_t)k0 * 512 + n0, 512,
                          g_pfc1 + (size_t)z * FC1_MN + m0 * 512 + n0, 128);
            } else {
                int j = job - 288;                 // 0..95
                int z = j >> 3, n0 = (j & 7) * 64;
                int k0 = z * 192;
                gemm_tile(half, ht, sbase,
                          g_ent + k0, PREDK,
                          predW1 + (size_t)k0 * 512 + n0, 512,
                          g_ppred + (size_t)z * PRED_MN + n0, 192);
            }
        }
        grid_sync();

        // ---- P2: fc1 finish -> u (+ pred finish on iter 0) ----
        nj = (it == 0) ? 256 : 192;
        for (int job = wid; job < nj; job += wstride) {
            if (job < 192) finish1_job(half, ht, sbase, job, Vrb1, VrW2, Vrb2, ArW, Arb);
            else           pred_finish_job(half, ht, sbase, job - 192,
                                           predb1, predW2, predb2, out_rel);
        }
        grid_sync();

        // ---- P3: gate GEMM partials (288) ----
        for (int job = wid; job < 288; job += wstride) {
            int z = job / 36, rem = job % 36;
            int m0 = (rem / 12) * 64, n0 = (rem % 12) * 64;
            int k0 = z * 192;
            gemm_tile(half, ht, sbase,
                      g_X2 + (size_t)m0 * KDIM + k0, KDIM,
                      gateW + (size_t)k0 * 768 + n0, 768,
                      g_pgate + (size_t)z * GATE_MN + m0 * 768 + n0, 192);
        }
        grid_sync();

        // ---- P4: gate blend; in-place e update + X1/X2 scatter ----
        bool last = (it == 4);
        int tg = blockIdx.x * 512 + threadIdx.x;
        for (int q = tg; q < GATE_MN / 4; q += nb * 512) {
            int idx = q * 4;
            int r = idx / 768, n = idx - r * 768;
            int p = r >> 6, b = r & 63;
            float4 s = *(const float4*)(gateb + n);
            #pragma unroll
            for (int z = 0; z < KS_GATE; z++) {
                float4 pv = ldcg4(g_pgate + (size_t)z * GATE_MN + idx);
                s.x += pv.x; s.y += pv.y; s.z += pv.z; s.w += pv.w;
            }
            float4 uv = ldcg4(g_X2 + (size_t)r * KDIM + n);   // u (left half)
            float4 ev = ldcg4(g_e + idx);
            float4 res; float gg;
            gg = sigmoidf(s.x); res.x = gg * ev.x + (1.0f - gg) * uv.x;
            gg = sigmoidf(s.y); res.y = gg * ev.y + (1.0f - gg) * uv.y;
            gg = sigmoidf(s.z); res.z = gg * ev.z + (1.0f - gg) * uv.z;
            gg = sigmoidf(s.w); res.w = gg * ev.w + (1.0f - gg) * uv.w;
            if (last) {
                *(float4*)(out_final + (size_t)b * PREDK + p * DIM + n) = res;
            } else {
                stcg4(g_e + idx, res);
                stcg4(g_X2 + (size_t)r * KDIM + 768 + n, res);
                stcg4(g_X1 + (size_t)(D1ROW[p] * 64 + b) * KDIM + D1OFF[p] + n, res);
                stcg4(g_X1 + (size_t)(D2ROW[p] * 64 + b) * KDIM + D2OFF[p] + n, res);
            }
        }
        if (!last) grid_sync();
    }
}

// ---------------------------------------------------------------------------
// Launcher
// ---------------------------------------------------------------------------
extern "C" void kernel_launch(void* const* d_in, const int* in_sizes, int n_in,
                              void* d_out, int out_size)
{
    const float* encoding = (const float*)d_in[0];
    const int*   ent_pos  = (const int*)  d_in[1];
    const float* Ar_W     = (const float*)d_in[2];
    const float* Ar_b     = (const float*)d_in[3];
    const float* Vr_W1    = (const float*)d_in[4];
    const float* Vr_b1    = (const float*)d_in[5];
    const float* Vr_W2    = (const float*)d_in[6];
    const float* Vr_b2    = (const float*)d_in[7];
    const float* gate_W   = (const float*)d_in[8];
    const float* gate_b   = (const float*)d_in[9];
    const float* pred_W1  = (const float*)d_in[10];
    const float* pred_b1  = (const float*)d_in[11];
    const float* pred_W2  = (const float*)d_in[12];
    const float* pred_b2  = (const float*)d_in[13];
    const float* proj_W   = (const float*)d_in[14];
    const float* proj_b   = (const float*)d_in[15];

    float* out = (float*)d_out;
    float* out_rel   = out;              // (64,5)
    float* out_score = out + 320;        // (64,3)
    float* out_final = out + 512;        // (64,3,768)

    int dev = 0;
    cudaGetDevice(&dev);
    int sms = 148;
    cudaDeviceGetAttribute(&sms, cudaDevAttrMultiProcessorCount, dev);

    cudaFuncSetAttribute(fused_kernel,
                         cudaFuncAttributeMaxDynamicSharedMemorySize,
                         TOTAL_SMEM_B);

    fused_kernel<<<sms, 512, TOTAL_SMEM_B>>>(
        encoding, ent_pos, Ar_W, Ar_b,
        Vr_W1, Vr_b1, Vr_W2, Vr_b2,
        gate_W, gate_b,
        pred_W1, pred_b1, pred_W2, pred_b2,
        proj_W, proj_b,
        out_rel, out_score, out_final);

    (void)in_sizes; (void)n_in; (void)out_size;
}